// round 16
// baseline (speedup 1.0000x reference)
#include <cuda_runtime.h>

// Single-pass IndRNN scan, decoupled lookback (R7 register-buffer body).
// h_t = relu(x_t + w*h_{t-1}), w >= 0. Chunk map g(h) = max(M, A + P*h),
// P = w^L, closed under composition.
// NO prologue kernel: the monotonically increasing ticket counter supplies
// both the virtual block id (vid & 8191) and the launch epoch
// ((vid >> 13) + 1), since each launch consumes exactly NBLK = 2^13 tickets.

static constexpr int T     = 2048;
static constexpr int B     = 32;
static constexpr int H     = 1024;
static constexpr int BH    = B * H;        // 32768
static constexpr int L     = 32;           // timesteps per chunk (registers)
static constexpr int K     = T / L;        // 64 chunks
static constexpr int TILES = BH / 256;     // 128 channel tiles
static constexpr int NBLK  = TILES * K;    // 8192 = 2^13 blocks

// Slot per (k, c): {M, A, h, status}; status = 2*epoch (agg) | 2*epoch+1 (incl).
__device__ float4   g_slot[(size_t)K * BH];   // 32 MB (mostly L2-resident)
__device__ unsigned g_ticket;                 // never reset; monotonic

__device__ __forceinline__ void st_slot(float4* p, float m, float a, float h,
                                        unsigned status)
{
    asm volatile("st.volatile.global.v4.f32 [%0], {%1, %2, %3, %4};"
                 :: "l"(p), "f"(m), "f"(a), "f"(h),
                    "f"(__uint_as_float(status)) : "memory");
}
__device__ __forceinline__ float4 ld_slot(const float4* p)
{
    float4 v;
    asm volatile("ld.volatile.global.v4.f32 {%0, %1, %2, %3}, [%4];"
                 : "=f"(v.x), "=f"(v.y), "=f"(v.z), "=f"(v.w) : "l"(p)
                 : "memory");
    return v;
}

__global__ __launch_bounds__(256)
void indrnn_onepass(const float* __restrict__ x,
                    const float* __restrict__ h0,
                    const float* __restrict__ w,
                    float* __restrict__ out)
{
    __shared__ unsigned s_vid;
    if (threadIdx.x == 0) s_vid = atomicAdd(&g_ticket, 1u);
    __syncthreads();
    const unsigned ticket = s_vid;
    const unsigned epoch  = (ticket >> 13) + 1u;     // launch-consistent, != 0
    const unsigned vid    = ticket & (NBLK - 1u);
    const int tile = vid & (TILES - 1);
    const int k    = vid >> 7;                       // TILES = 128
    const int c    = tile * 256 + threadIdx.x;

    const float wc  = __ldg(&w[c & (H - 1)]);
    const float h0c = __ldg(&h0[c]);
    float Pc = wc;
#pragma unroll
    for (int s = 0; s < 5; s++) Pc *= Pc;            // wc^32

    const float* xp = x + (size_t)k * L * BH + c;

    // Load the whole chunk into registers (the only read of x).
    float buf[L];
#pragma unroll
    for (int i = 0; i < L; i++) buf[i] = __ldcs(xp + i * BH);

    // Chunk aggregate: g(h) = max(M, A + Pc*h).
    float M = (wc > 0.0f) ? __int_as_float(0xff800000) : 0.0f;  // -inf / 0
    float A = 0.0f;
#pragma unroll
    for (int i = 0; i < L; i++) {
        M = fmaxf(0.0f, fmaf(wc, M, buf[i]));
        A = fmaf(wc, A, buf[i]);
    }

    // Acquire h_in. Fast path: predecessor inclusive already visible.
    float hin;
    if (k == 0) {
        hin = h0c;
    } else {
        float4 p = ld_slot(&g_slot[(size_t)(k - 1) * BH + c]);
        if (__float_as_uint(p.w) == 2u * epoch + 1u) {
            hin = p.z;                               // skip aggregate publish
        } else {
            // Slow path: publish aggregate so successors can pass over us,
            // then compose aggregates backward until an inclusive (or h0).
            st_slot(&g_slot[(size_t)k * BH + c], M, A, 0.0f, 2u * epoch);
            float Ms = __int_as_float(0xff800000);   // identity map
            float As = 0.0f;
            float Ps = 1.0f;
            int   j  = k - 1;
            for (;;) {
                float4 s = ld_slot(&g_slot[(size_t)j * BH + c]);
                unsigned st = __float_as_uint(s.w);
                if (st == 2u * epoch + 1u) {         // inclusive available
                    hin = fmaxf(Ms, fmaf(Ps, s.z, As));
                    break;
                }
                if (st == 2u * epoch) {              // aggregate: compose
                    const float nM = fmaxf(Ms, fmaf(Ps, s.x, As));
                    As = fmaf(Ps, s.y, As);
                    Ms = nM;
                    Ps *= Pc;
                    if (--j < 0) { hin = fmaxf(Ms, fmaf(Ps, h0c, As)); break; }
                    continue;
                }
                __nanosleep(32);                     // j not started yet
            }
        }
    }

    // Publish inclusive (bounds lookback depth for later waves).
    if (k < K - 1) {
        const float hout = fmaxf(M, fmaf(Pc, hin, A));
        st_slot(&g_slot[(size_t)k * BH + c], M, A, hout, 2u * epoch + 1u);
    }

    // Emit: exact forward recursion from registers.
    float* op = out + (size_t)k * L * BH + c;
    float h = hin;
#pragma unroll
    for (int i = 0; i < L; i++) {
        h = fmaxf(fmaf(wc, h, buf[i]), 0.0f);
        __stcs(op + i * BH, h);
    }
}

extern "C" void kernel_launch(void* const* d_in, const int* in_sizes, int n_in,
                              void* d_out, int out_size)
{
    const float* x  = (const float*)d_in[0];   // (T, B, H)
    const float* h0 = (const float*)d_in[1];   // (B, H)
    const float* w  = (const float*)d_in[2];   // (H,)
    float* out      = (float*)d_out;

    indrnn_onepass<<<NBLK, 256>>>(x, h0, w, out);
}